// round 1
// baseline (speedup 1.0000x reference)
#include <cuda_runtime.h>
#include <math.h>

// OutputNetwork: per-pair radial MLP (2-sparse basis -> 128 -> 128 -> 112)
// + spherical-harmonic contraction, reduced over neighbors b, softplus, mask.
//
// Grid: one block per (z,a) pair slot. 128 threads. All weights in dynamic SMEM.

#define THREADS 128
#define BCH 4           // neighbors processed per chunk (ILP depth)
#define NCHUNK 16       // 64 / BCH

// ---- SMEM layout (in floats) ----
// W1s   [32][128]   : 4096
// W2s   [128][128]  : 16384
// W3s   [128][112]  : 14336
// geos  [64][3]     : 192
// fz    [4][240]    : 960
// h1    [4][128]    : 512
// h2    [4][128]    : 512
// Rws   [4][112]    : 448
// ybuf  [4][8]      : 32   (y1[3], y2[5])
// cbuf  [4][2]      : 8
// ibuf  [4][2] int  : 8
// red   [4]         : 4
// misc  [2]         : 2    (featscale, mask[z,a])
#define OFF_W1   0
#define OFF_W2   4096
#define OFF_W3   20480
#define OFF_GEO  34816
#define OFF_FZ   35008
#define OFF_H1   35968
#define OFF_H2   36480
#define OFF_RW   36992
#define OFF_Y    37440
#define OFF_CB   37472
#define OFF_IB   37480
#define OFF_RED  37488
#define OFF_MISC 37492
#define SMEM_FLOATS 37494
#define SMEM_BYTES  (SMEM_FLOATS * 4)

__device__ __forceinline__ float ssp_f(float x) {
    // (softplus(5x) - log 2) / 5, overflow-safe
    float bx = 5.0f * x;
    return (fmaxf(bx, 0.0f) + log1pf(expf(-fabsf(bx))) - 0.69314718055994531f) * 0.2f;
}

__global__ void __launch_bounds__(THREADS, 1)
output_network_kernel(const float* __restrict__ rep,
                      const float* __restrict__ geo,
                      const float* __restrict__ mask,
                      const float* __restrict__ W1,
                      const float* __restrict__ W2,
                      const float* __restrict__ W3,
                      float* __restrict__ out)
{
    extern __shared__ float s[];
    float* W1s  = s + OFF_W1;
    float* W2s  = s + OFF_W2;
    float* W3s  = s + OFF_W3;
    float* geos = s + OFF_GEO;
    float* fz   = s + OFF_FZ;
    float* h1   = s + OFF_H1;
    float* h2   = s + OFF_H2;
    float* Rws  = s + OFF_RW;
    float* ybuf = s + OFF_Y;
    float* cbuf = s + OFF_CB;
    int*   ibuf = (int*)(s + OFF_IB);
    float* red  = s + OFF_RED;
    float* misc = s + OFF_MISC;

    const int t = threadIdx.x;
    const int z = blockIdx.x >> 6;
    const int a = blockIdx.x & 63;

    // ---- Load weights into SMEM (vectorized, coalesced) ----
    {
        const float4* g1 = (const float4*)W1;  float4* s1 = (float4*)W1s;
        const float4* g2 = (const float4*)W2;  float4* s2 = (float4*)W2s;
        const float4* g3 = (const float4*)W3;  float4* s3 = (float4*)W3s;
        #pragma unroll 4
        for (int i = t; i < 1024; i += THREADS) s1[i] = g1[i];
        #pragma unroll 8
        for (int i = t; i < 4096; i += THREADS) s2[i] = g2[i];
        #pragma unroll 8
        for (int i = t; i < 3584; i += THREADS) s3[i] = g3[i];
        for (int i = t; i < 192; i += THREADS)  geos[i] = geo[z * 192 + i];
        // mask sum staged in h1 temporarily
        h1[t] = (t < 64) ? mask[z * 64 + t] : 0.0f;
    }
    __syncthreads();
    if (t == 0) {
        float na = 0.0f;
        #pragma unroll
        for (int i = 0; i < 64; i++) na += h1[i];
        misc[0] = rsqrtf(na);          // featscale
        misc[1] = mask[z * 64 + a];    // output mask
    }
    __syncthreads();

    const float gax = geos[a * 3 + 0];
    const float gay = geos[a * 3 + 1];
    const float gaz = geos[a * 3 + 2];

    const float RS32  = 0.17677669529663687f;   // 1/sqrt(32)
    const float RS128 = 0.08838834764831843f;   // 1/sqrt(128)
    const float NORM0 = 0.125f;                 // 1/sqrt(1*64)
    const float NORM1 = 0.10206207261596575f;   // 1/sqrt(3*32)
    const float NORM2 = 0.11180339887498948f;   // 1/sqrt(5*16)
    const float S3  = 1.7320508075688772f;
    const float S5  = 2.2360679774997896f;
    const float S15 = 3.872983346207417f;

    float total = 0.0f;

    for (int c = 0; c < NCHUNK; c++) {
        const int b0 = c * BCH;

        // ---- stage feats for 4 neighbors (scaled) ----
        {
            const float fscale = misc[0];
            const float* rbase = rep + (size_t)(z * 64 + b0) * 240;
            #pragma unroll
            for (int i = t; i < BCH * 240; i += THREADS)
                fz[i] = rbase[i] * fscale;
        }

        // ---- per-neighbor geometry / SH / basis coefficients ----
        if (t < BCH) {
            const int b = b0 + t;
            const float rx = gax - geos[b * 3 + 0];
            const float ry = gay - geos[b * 3 + 1];
            const float rz = gaz - geos[b * 3 + 2];
            const float r2 = rx * rx + ry * ry + rz * rz;
            const float r  = sqrtf(fmaxf(r2, 1e-12f));
            const float nzf = (r2 > 1e-10f) ? 1.0f : 0.0f;
            const float inv = 1.0f / r;
            const float xh = rx * inv, yh = ry * inv, zh = rz * inv;
            float* y = ybuf + t * 8;
            y[0] = S3 * xh * nzf;
            y[1] = S3 * yh * nzf;
            y[2] = S3 * zh * nzf;
            y[3] = S15 * xh * yh * nzf;
            y[4] = S15 * yh * zh * nzf;
            y[5] = 0.5f * S5 * (3.0f * zh * zh - 1.0f) * nzf;
            y[6] = S15 * xh * zh * nzf;
            y[7] = 0.5f * S15 * (xh * xh - yh * yh) * nzf;
            // cosine basis: at most 2 nonzero entries
            const float u = r * 3.1f;            // r / (10/31)
            int i0 = (int)floorf(u);
            const float d0 = u - (float)i0;
            float sv, cv;
            sincosf(1.5707963267948966f * d0, &sv, &cv);
            cbuf[t * 2 + 0] = (i0 <= 31) ? cv : 0.0f;       // basis at i0
            cbuf[t * 2 + 1] = (i0 <= 30) ? sv : 0.0f;       // basis at i0+1
            ibuf[t * 2 + 0] = min(i0, 31) < 0 ? 0 : min(i0, 31);
            ibuf[t * 2 + 1] = min(i0 + 1, 31);
        }
        __syncthreads();

        // ---- layer 1 (2-sparse basis) + ssp ----
        #pragma unroll
        for (int bi = 0; bi < BCH; bi++) {
            const float pre = (cbuf[bi * 2 + 0] * W1s[ibuf[bi * 2 + 0] * 128 + t] +
                               cbuf[bi * 2 + 1] * W1s[ibuf[bi * 2 + 1] * 128 + t]) * RS32;
            h1[bi * 128 + t] = ssp_f(pre);
        }
        __syncthreads();

        // ---- layer 2: h2 = ssp(h1 @ W2 / sqrt(128)) ----
        {
            float a0 = 0.f, a1 = 0.f, a2 = 0.f, a3 = 0.f;
            #pragma unroll 4
            for (int k = 0; k < 128; k += 4) {
                const float4 x0 = *(const float4*)&h1[k];
                const float4 x1 = *(const float4*)&h1[128 + k];
                const float4 x2 = *(const float4*)&h1[256 + k];
                const float4 x3 = *(const float4*)&h1[384 + k];
                const float w0 = W2s[(k + 0) * 128 + t];
                const float w1 = W2s[(k + 1) * 128 + t];
                const float w2 = W2s[(k + 2) * 128 + t];
                const float w3 = W2s[(k + 3) * 128 + t];
                a0 = fmaf(x0.x, w0, a0); a0 = fmaf(x0.y, w1, a0);
                a0 = fmaf(x0.z, w2, a0); a0 = fmaf(x0.w, w3, a0);
                a1 = fmaf(x1.x, w0, a1); a1 = fmaf(x1.y, w1, a1);
                a1 = fmaf(x1.z, w2, a1); a1 = fmaf(x1.w, w3, a1);
                a2 = fmaf(x2.x, w0, a2); a2 = fmaf(x2.y, w1, a2);
                a2 = fmaf(x2.z, w2, a2); a2 = fmaf(x2.w, w3, a2);
                a3 = fmaf(x3.x, w0, a3); a3 = fmaf(x3.y, w1, a3);
                a3 = fmaf(x3.z, w2, a3); a3 = fmaf(x3.w, w3, a3);
            }
            h2[t]       = ssp_f(a0 * RS128);
            h2[128 + t] = ssp_f(a1 * RS128);
            h2[256 + t] = ssp_f(a2 * RS128);
            h2[384 + t] = ssp_f(a3 * RS128);
        }
        __syncthreads();

        // ---- layer 3: Rw = h2 @ W3 / sqrt(128) (112 outputs) ----
        if (t < 112) {
            float a0 = 0.f, a1 = 0.f, a2 = 0.f, a3 = 0.f;
            #pragma unroll 4
            for (int k = 0; k < 128; k += 4) {
                const float4 x0 = *(const float4*)&h2[k];
                const float4 x1 = *(const float4*)&h2[128 + k];
                const float4 x2 = *(const float4*)&h2[256 + k];
                const float4 x3 = *(const float4*)&h2[384 + k];
                const float w0 = W3s[(k + 0) * 112 + t];
                const float w1 = W3s[(k + 1) * 112 + t];
                const float w2 = W3s[(k + 2) * 112 + t];
                const float w3 = W3s[(k + 3) * 112 + t];
                a0 = fmaf(x0.x, w0, a0); a0 = fmaf(x0.y, w1, a0);
                a0 = fmaf(x0.z, w2, a0); a0 = fmaf(x0.w, w3, a0);
                a1 = fmaf(x1.x, w0, a1); a1 = fmaf(x1.y, w1, a1);
                a1 = fmaf(x1.z, w2, a1); a1 = fmaf(x1.w, w3, a1);
                a2 = fmaf(x2.x, w0, a2); a2 = fmaf(x2.y, w1, a2);
                a2 = fmaf(x2.z, w2, a2); a2 = fmaf(x2.w, w3, a2);
                a3 = fmaf(x3.x, w0, a3); a3 = fmaf(x3.y, w1, a3);
                a3 = fmaf(x3.z, w2, a3); a3 = fmaf(x3.w, w3, a3);
            }
            Rws[0 * 112 + t] = a0 * RS128;
            Rws[1 * 112 + t] = a1 * RS128;
            Rws[2 * 112 + t] = a2 * RS128;
            Rws[3 * 112 + t] = a3 * RS128;
        }
        __syncthreads();

        // ---- combine: Σ_b Σ_l norm_l R_l[m] (Y_l · f_block[m]) ----
        if (t < 112) {
            #pragma unroll
            for (int bi = 0; bi < BCH; bi++) {
                const float Rv = Rws[bi * 112 + t];
                const float* f = fz + bi * 240;
                const float* y = ybuf + bi * 8;
                float v;
                if (t < 64) {
                    v = Rv * f[t] * NORM0;
                } else if (t < 96) {
                    const int m = t - 64;
                    const float* fb = f + 64 + 3 * m;
                    v = Rv * NORM1 * (y[0] * fb[0] + y[1] * fb[1] + y[2] * fb[2]);
                } else {
                    const int m = t - 96;
                    const float* fb = f + 160 + 5 * m;
                    v = Rv * NORM2 * (y[3] * fb[0] + y[4] * fb[1] + y[5] * fb[2] +
                                      y[6] * fb[3] + y[7] * fb[4]);
                }
                total += v;
            }
        }
        __syncthreads();
    }

    // ---- block reduction ----
    #pragma unroll
    for (int o = 16; o > 0; o >>= 1)
        total += __shfl_xor_sync(0xffffffff, total, o);
    if ((t & 31) == 0) red[t >> 5] = total;
    __syncthreads();
    if (t == 0) {
        const float ssum = red[0] + red[1] + red[2] + red[3];
        const float bx = 5.0f * ssum;
        const float sp = (fmaxf(bx, 0.0f) + log1pf(expf(-fabsf(bx)))) * 0.2f;
        out[blockIdx.x] = sp * misc[1];
    }
}

extern "C" void kernel_launch(void* const* d_in, const int* in_sizes, int n_in,
                              void* d_out, int out_size)
{
    const float* rep  = (const float*)d_in[0];
    const float* geo  = (const float*)d_in[1];
    const float* mask = (const float*)d_in[2];
    const float* W1   = (const float*)d_in[3];
    const float* W2   = (const float*)d_in[4];
    const float* W3   = (const float*)d_in[5];
    float* out = (float*)d_out;

    cudaFuncSetAttribute(output_network_kernel,
                         cudaFuncAttributeMaxDynamicSharedMemorySize, SMEM_BYTES);
    output_network_kernel<<<64 * 64, THREADS, SMEM_BYTES>>>(rep, geo, mask, W1, W2, W3, out);
}

// round 2
// speedup vs baseline: 1.7383x; 1.7383x over previous
#include <cuda_runtime.h>
#include <math.h>

// OutputNetwork: per-pair radial MLP (2-sparse basis -> 128 -> 128 -> 112)
// + spherical-harmonic contraction, reduced over neighbors, softplus, mask.
//
// Persistent kernel: 148 CTAs x 512 threads, weights resident in SMEM.
// Each CTA loops over (z,a) tiles. Within a tile, 4 independent groups of
// 128 threads each process 4 neighbors, synchronized by NAMED barriers only.

#define THREADS 512
#define NTILES  4096
#define GRID    148

// ---- SMEM layout (floats) ----
#define OFF_W1   0        // [32][128]
#define OFF_W2   4096     // [128][128]
#define OFF_W3   20480    // [128][112]
#define OFF_GEO  34816    // [64][3]
#define OFF_FZ   35008    // [16][240]
#define OFF_H1   38848    // [16][128]
#define OFF_H2   40896    // [16][128]
#define OFF_Y    42944    // [16][8]
#define OFF_CB   43072    // [16][2]
#define OFF_IB   43104    // [16][2] int
#define OFF_RED  43136    // [16]
#define OFF_MISC 43152    // [2]
#define SMEM_FLOATS 43154
#define SMEM_BYTES  (SMEM_FLOATS * 4)

__device__ __forceinline__ float ssp_f(float x) {
    // (softplus(5x) - log 2) / 5, fast-math version (err << 1e-5)
    float bx = 5.0f * x;
    float e  = __expf(-fabsf(bx));
    return (fmaxf(bx, 0.0f) + __logf(1.0f + e) - 0.69314718055994531f) * 0.2f;
}

__device__ __forceinline__ void barg(int id) {
    asm volatile("bar.sync %0, 128;" :: "r"(id) : "memory");
}

__global__ void __launch_bounds__(THREADS, 1)
output_network_kernel(const float* __restrict__ rep,
                      const float* __restrict__ geo,
                      const float* __restrict__ mask,
                      const float* __restrict__ W1,
                      const float* __restrict__ W2,
                      const float* __restrict__ W3,
                      float* __restrict__ out)
{
    extern __shared__ float s[];
    float* W1s  = s + OFF_W1;
    float* W2s  = s + OFF_W2;
    float* W3s  = s + OFF_W3;
    float* geos = s + OFF_GEO;
    float* fz   = s + OFF_FZ;
    float* h1   = s + OFF_H1;
    float* h2   = s + OFF_H2;
    float* ybuf = s + OFF_Y;
    float* cbuf = s + OFF_CB;
    int*   ibuf = (int*)(s + OFF_IB);
    float* red  = s + OFF_RED;
    float* misc = s + OFF_MISC;

    const int t   = threadIdx.x;
    const int g   = t >> 7;        // group 0..3
    const int col = t & 127;       // within-group tid
    const int bar_id = g + 1;

    // ---- Load weights once (persistent CTA) ----
    {
        const float4* g1 = (const float4*)W1;  float4* s1 = (float4*)W1s;
        const float4* g2 = (const float4*)W2;  float4* s2 = (float4*)W2s;
        const float4* g3 = (const float4*)W3;  float4* s3 = (float4*)W3s;
        #pragma unroll 2
        for (int i = t; i < 1024; i += THREADS) s1[i] = g1[i];
        #pragma unroll 8
        for (int i = t; i < 4096; i += THREADS) s2[i] = g2[i];
        #pragma unroll 7
        for (int i = t; i < 3584; i += THREADS) s3[i] = g3[i];
    }
    __syncthreads();

    const float RS32  = 0.17677669529663687f;   // 1/sqrt(32)
    const float RS128 = 0.08838834764831843f;   // 1/sqrt(128)
    const float NORM0 = 0.125f;                 // 1/sqrt(1*64)
    const float NORM1 = 0.10206207261596575f;   // 1/sqrt(3*32)
    const float NORM2 = 0.11180339887498948f;   // 1/sqrt(5*16)
    const float S3  = 1.7320508075688772f;
    const float S5  = 2.2360679774997896f;
    const float S15 = 3.872983346207417f;

    for (int tile = blockIdx.x; tile < NTILES; tile += GRID) {
        const int z = tile >> 6;
        const int a = tile & 63;

        // ---- per-tile staging: geometry + mask sum ----
        if (t < 64) ybuf[t] = mask[z * 64 + t];
        for (int i = t; i < 192; i += THREADS) geos[i] = geo[z * 192 + i];
        __syncthreads();
        if (t == 0) {
            float na = 0.0f;
            #pragma unroll
            for (int i = 0; i < 64; i++) na += ybuf[i];
            misc[0] = rsqrtf(na);
            misc[1] = mask[z * 64 + a];
        }
        __syncthreads();

        const float gax = geos[a * 3 + 0];
        const float gay = geos[a * 3 + 1];
        const float gaz = geos[a * 3 + 2];
        const float fscale = misc[0];

        float total = 0.0f;

        #pragma unroll 1
        for (int c = 0; c < 4; c++) {
            const int nb = g * 4;                // group's local neighbor base (0..12)
            const int b0 = c * 16 + nb;          // global neighbor base for this group

            // ---- stage feats for this group's 4 neighbors (scaled, float4) ----
            {
                const float4* rbase = (const float4*)(rep + (size_t)(z * 64 + b0) * 240);
                float4* fdst = (float4*)(fz + nb * 240);
                #pragma unroll 2
                for (int i = col; i < 240; i += 128) {
                    float4 v = rbase[i];
                    v.x *= fscale; v.y *= fscale; v.z *= fscale; v.w *= fscale;
                    fdst[i] = v;
                }
            }
            // ---- SH + basis coefficients for 4 neighbors (threads col<4) ----
            if (col < 4) {
                const int b = b0 + col;
                const int nl = nb + col;
                const float rx = gax - geos[b * 3 + 0];
                const float ry = gay - geos[b * 3 + 1];
                const float rz = gaz - geos[b * 3 + 2];
                const float r2 = rx * rx + ry * ry + rz * rz;
                const float r  = sqrtf(fmaxf(r2, 1e-12f));
                const float nzf = (r2 > 1e-10f) ? 1.0f : 0.0f;
                const float inv = 1.0f / r;
                const float xh = rx * inv, yh = ry * inv, zh = rz * inv;
                float* y = ybuf + nl * 8;
                y[0] = S3 * xh * nzf;
                y[1] = S3 * yh * nzf;
                y[2] = S3 * zh * nzf;
                y[3] = S15 * xh * yh * nzf;
                y[4] = S15 * yh * zh * nzf;
                y[5] = 0.5f * S5 * (3.0f * zh * zh - 1.0f) * nzf;
                y[6] = S15 * xh * zh * nzf;
                y[7] = 0.5f * S15 * (xh * xh - yh * yh) * nzf;
                // cosine basis: at most 2 adjacent nonzero entries
                const float u = r * 3.1f;        // r / (10/31)
                int i0 = (int)floorf(u);
                const float d0 = u - (float)i0;
                float sv, cv;
                __sincosf(1.5707963267948966f * d0, &sv, &cv);
                cbuf[nl * 2 + 0] = (i0 <= 31) ? cv : 0.0f;
                cbuf[nl * 2 + 1] = (i0 <= 30) ? sv : 0.0f;
                ibuf[nl * 2 + 0] = min(i0, 31) < 0 ? 0 : min(i0, 31);
                ibuf[nl * 2 + 1] = min(i0 + 1, 31);
            }
            barg(bar_id);

            // ---- layer 1 (2-sparse basis) + ssp ----
            #pragma unroll
            for (int bi = 0; bi < 4; bi++) {
                const int nl = nb + bi;
                const float pre = (cbuf[nl * 2 + 0] * W1s[ibuf[nl * 2 + 0] * 128 + col] +
                                   cbuf[nl * 2 + 1] * W1s[ibuf[nl * 2 + 1] * 128 + col]) * RS32;
                h1[nl * 128 + col] = ssp_f(pre);
            }
            barg(bar_id);

            // ---- layer 2: h2 = ssp(h1 @ W2 / sqrt(128)) ----
            {
                const float* x0p = h1 + (nb + 0) * 128;
                const float* x1p = h1 + (nb + 1) * 128;
                const float* x2p = h1 + (nb + 2) * 128;
                const float* x3p = h1 + (nb + 3) * 128;
                float a0 = 0.f, a1 = 0.f, a2 = 0.f, a3 = 0.f;
                #pragma unroll 4
                for (int k = 0; k < 128; k += 4) {
                    const float4 x0 = *(const float4*)&x0p[k];
                    const float4 x1 = *(const float4*)&x1p[k];
                    const float4 x2 = *(const float4*)&x2p[k];
                    const float4 x3 = *(const float4*)&x3p[k];
                    const float w0 = W2s[(k + 0) * 128 + col];
                    const float w1 = W2s[(k + 1) * 128 + col];
                    const float w2 = W2s[(k + 2) * 128 + col];
                    const float w3 = W2s[(k + 3) * 128 + col];
                    a0 = fmaf(x0.x, w0, a0); a0 = fmaf(x0.y, w1, a0);
                    a0 = fmaf(x0.z, w2, a0); a0 = fmaf(x0.w, w3, a0);
                    a1 = fmaf(x1.x, w0, a1); a1 = fmaf(x1.y, w1, a1);
                    a1 = fmaf(x1.z, w2, a1); a1 = fmaf(x1.w, w3, a1);
                    a2 = fmaf(x2.x, w0, a2); a2 = fmaf(x2.y, w1, a2);
                    a2 = fmaf(x2.z, w2, a2); a2 = fmaf(x2.w, w3, a2);
                    a3 = fmaf(x3.x, w0, a3); a3 = fmaf(x3.y, w1, a3);
                    a3 = fmaf(x3.z, w2, a3); a3 = fmaf(x3.w, w3, a3);
                }
                h2[(nb + 0) * 128 + col] = ssp_f(a0 * RS128);
                h2[(nb + 1) * 128 + col] = ssp_f(a1 * RS128);
                h2[(nb + 2) * 128 + col] = ssp_f(a2 * RS128);
                h2[(nb + 3) * 128 + col] = ssp_f(a3 * RS128);
            }
            barg(bar_id);

            // ---- layer 3 (Rw in registers) fused with SH contraction ----
            if (col < 112) {
                const float* x0p = h2 + (nb + 0) * 128;
                const float* x1p = h2 + (nb + 1) * 128;
                const float* x2p = h2 + (nb + 2) * 128;
                const float* x3p = h2 + (nb + 3) * 128;
                float a0 = 0.f, a1 = 0.f, a2 = 0.f, a3 = 0.f;
                #pragma unroll 4
                for (int k = 0; k < 128; k += 4) {
                    const float4 x0 = *(const float4*)&x0p[k];
                    const float4 x1 = *(const float4*)&x1p[k];
                    const float4 x2 = *(const float4*)&x2p[k];
                    const float4 x3 = *(const float4*)&x3p[k];
                    const float w0 = W3s[(k + 0) * 112 + col];
                    const float w1 = W3s[(k + 1) * 112 + col];
                    const float w2 = W3s[(k + 2) * 112 + col];
                    const float w3 = W3s[(k + 3) * 112 + col];
                    a0 = fmaf(x0.x, w0, a0); a0 = fmaf(x0.y, w1, a0);
                    a0 = fmaf(x0.z, w2, a0); a0 = fmaf(x0.w, w3, a0);
                    a1 = fmaf(x1.x, w0, a1); a1 = fmaf(x1.y, w1, a1);
                    a1 = fmaf(x1.z, w2, a1); a1 = fmaf(x1.w, w3, a1);
                    a2 = fmaf(x2.x, w0, a2); a2 = fmaf(x2.y, w1, a2);
                    a2 = fmaf(x2.z, w2, a2); a2 = fmaf(x2.w, w3, a2);
                    a3 = fmaf(x3.x, w0, a3); a3 = fmaf(x3.y, w1, a3);
                    a3 = fmaf(x3.z, w2, a3); a3 = fmaf(x3.w, w3, a3);
                }
                float Rv[4] = { a0 * RS128, a1 * RS128, a2 * RS128, a3 * RS128 };
                #pragma unroll
                for (int bi = 0; bi < 4; bi++) {
                    const int nl = nb + bi;
                    const float* f = fz + nl * 240;
                    const float* y = ybuf + nl * 8;
                    float v;
                    if (col < 64) {
                        v = Rv[bi] * f[col] * NORM0;
                    } else if (col < 96) {
                        const int m = col - 64;
                        const float* fb = f + 64 + 3 * m;
                        v = Rv[bi] * NORM1 * (y[0] * fb[0] + y[1] * fb[1] + y[2] * fb[2]);
                    } else {
                        const int m = col - 96;
                        const float* fb = f + 160 + 5 * m;
                        v = Rv[bi] * NORM2 * (y[3] * fb[0] + y[4] * fb[1] + y[5] * fb[2] +
                                              y[6] * fb[3] + y[7] * fb[4]);
                    }
                    total += v;
                }
            }
            barg(bar_id);   // protect fz/ybuf/cbuf before next chunk's staging
        }

        // ---- block reduction over all 512 threads ----
        __syncthreads();
        #pragma unroll
        for (int o = 16; o > 0; o >>= 1)
            total += __shfl_xor_sync(0xffffffff, total, o);
        if ((t & 31) == 0) red[t >> 5] = total;
        __syncthreads();
        if (t == 0) {
            float ssum = 0.0f;
            #pragma unroll
            for (int w = 0; w < 16; w++) ssum += red[w];
            const float bx = 5.0f * ssum;
            const float sp = (fmaxf(bx, 0.0f) + log1pf(expf(-fabsf(bx)))) * 0.2f;
            out[tile] = sp * misc[1];
        }
        __syncthreads();   // red/ybuf/misc reuse safety for next tile
    }
}

extern "C" void kernel_launch(void* const* d_in, const int* in_sizes, int n_in,
                              void* d_out, int out_size)
{
    const float* rep  = (const float*)d_in[0];
    const float* geo  = (const float*)d_in[1];
    const float* mask = (const float*)d_in[2];
    const float* W1   = (const float*)d_in[3];
    const float* W2   = (const float*)d_in[4];
    const float* W3   = (const float*)d_in[5];
    float* out = (float*)d_out;

    cudaFuncSetAttribute(output_network_kernel,
                         cudaFuncAttributeMaxDynamicSharedMemorySize, SMEM_BYTES);
    output_network_kernel<<<GRID, THREADS, SMEM_BYTES>>>(rep, geo, mask, W1, W2, W3, out);
}

// round 7
// speedup vs baseline: 11.8934x; 6.8421x over previous
#include <cuda_runtime.h>
#include <cuda_fp16.h>
#include <math.h>

// OutputNetwork via mma.sync (HMMA) tensor cores, sm_103-safe PTX only.
// Per (z, a-half) CTA: 256 threads = 2 groups x 4 warps. Each group iterates
// 8 tiles of M=128 pairs (2 a x 64 b): h1 prologue (2-sparse cosine basis,
// fused ssp) -> fp16 GEMM1 (128x128x128) -> ssp epilogue -> fp16 GEMM2
// (128x112x128) -> fused SH contraction + reduction. All phases warp-local.

#define THREADS 256
#define GRIDX   128

// ---- dynamic SMEM byte offsets ----
#define OFF_AB0   0         // group0 A/H1/H2 fp16 [128 rows][136 halves] (272B rows)
#define OFF_AB1   34816     // group1
#define OFF_W2T   69632     // W2^T fp16 [128 n][136]
#define OFF_W3T   104448    // W3^T fp16 [112 n][136]
#define OFF_W1S   134912    // W1 fp32 [32][132]
#define OFF_FEAT  151808    // feats fp32 [64][244]
#define OFF_GEO   214272    // fp32 [64][3]
#define OFF_RED   215040    // 16 floats
#define OFF_MISC  215104    // fscale
#define SMEM_BYTES 215168

__device__ __forceinline__ unsigned smem_u32(const void* p) {
    unsigned a;
    asm("{ .reg .u64 t; cvta.to.shared.u64 t, %1; cvt.u32.u64 %0, t; }" : "=r"(a) : "l"(p));
    return a;
}

__device__ __forceinline__ void ldm4(unsigned& r0, unsigned& r1, unsigned& r2, unsigned& r3,
                                     unsigned addr) {
    asm volatile("ldmatrix.sync.aligned.m8n8.x4.shared.b16 {%0, %1, %2, %3}, [%4];"
                 : "=r"(r0), "=r"(r1), "=r"(r2), "=r"(r3) : "r"(addr));
}

__device__ __forceinline__ void mma16816(float& d0, float& d1, float& d2, float& d3,
                                         unsigned a0, unsigned a1, unsigned a2, unsigned a3,
                                         unsigned b0, unsigned b1) {
    asm volatile("mma.sync.aligned.m16n8k16.row.col.f32.f16.f16.f32 "
                 "{%0, %1, %2, %3}, {%4, %5, %6, %7}, {%8, %9}, {%0, %1, %2, %3};"
                 : "+f"(d0), "+f"(d1), "+f"(d2), "+f"(d3)
                 : "r"(a0), "r"(a1), "r"(a2), "r"(a3), "r"(b0), "r"(b1));
}

__device__ __forceinline__ void barg(int id) {
    asm volatile("bar.sync %0, 128;" :: "r"(id) : "memory");
}

__device__ __forceinline__ float ssp_f(float x) {
    // (softplus(5x) - log 2) / 5
    float bx = 5.0f * x;
    float e  = __expf(-fabsf(bx));
    return (fmaxf(bx, 0.0f) + __logf(1.0f + e) - 0.69314718055994531f) * 0.2f;
}

__device__ __forceinline__ unsigned packh2(float a, float b) {
    __half2 h = __floats2half2_rn(a, b);   // .x = a (low), .y = b (high)
    return reinterpret_cast<unsigned&>(h);
}

// Warp-level GEMM: D[M=32 rows of this warp][N = NT*8] = A(128-K fp16) x B^T.
// c layout: c[mt*NT + nt][4] fragments of m16n8k16. Zeroed inside.
template<int NT>
__device__ __forceinline__ void warp_gemm(float (*c)[4], unsigned Abase, unsigned Bbase,
                                          int w, int lane) {
    #pragma unroll
    for (int i = 0; i < 2 * NT; i++) {
        c[i][0] = 0.f; c[i][1] = 0.f; c[i][2] = 0.f; c[i][3] = 0.f;
    }
    const int mi  = lane >> 3;    // ldmatrix quadrant 0..3
    const int l7  = lane & 7;
    const int ar  = 32 * w + (mi & 1) * 8 + l7;  // A row for this lane's quadrant
    const int ac  = (mi >> 1) * 8;               // A col offset (k-half)
    const int bk  = (mi & 1) * 8;                // B k-half
    const int bts = (mi >> 1);                   // B tile select within pair

    #pragma unroll 1
    for (int ks = 0; ks < 8; ks++) {
        unsigned af[2][4];
        #pragma unroll
        for (int mt = 0; mt < 2; mt++) {
            unsigned ad = Abase + (unsigned)((ar + 16 * mt) * 272 + (ks * 16 + ac) * 2);
            ldm4(af[mt][0], af[mt][1], af[mt][2], af[mt][3], ad);
        }
        unsigned bf[NT][2];
        #pragma unroll
        for (int p = 0; p < NT / 2; p++) {
            int ntl = 2 * p + bts;
            unsigned bd = Bbase + (unsigned)((ntl * 8 + l7) * 272 + (ks * 16 + bk) * 2);
            unsigned r0, r1, r2, r3;
            ldm4(r0, r1, r2, r3, bd);
            bf[2 * p][0] = r0;  bf[2 * p][1] = r1;
            bf[2 * p + 1][0] = r2;  bf[2 * p + 1][1] = r3;
        }
        #pragma unroll
        for (int mt = 0; mt < 2; mt++)
            #pragma unroll
            for (int nt = 0; nt < NT; nt++)
                mma16816(c[mt * NT + nt][0], c[mt * NT + nt][1],
                         c[mt * NT + nt][2], c[mt * NT + nt][3],
                         af[mt][0], af[mt][1], af[mt][2], af[mt][3],
                         bf[nt][0], bf[nt][1]);
    }
}

__global__ void __launch_bounds__(THREADS, 1)
output_network_kernel(const float* __restrict__ rep,
                      const float* __restrict__ geo,
                      const float* __restrict__ mask,
                      const float* __restrict__ W1,
                      const float* __restrict__ W2,
                      const float* __restrict__ W3,
                      float* __restrict__ out)
{
    extern __shared__ char smc[];
    float*  W1S    = (float*)(smc + OFF_W1S);
    float*  featsF = (float*)(smc + OFF_FEAT);
    float*  geoF   = (float*)(smc + OFF_GEO);
    float*  redF   = (float*)(smc + OFF_RED);
    float*  miscF  = (float*)(smc + OFF_MISC);
    __half* W2Th   = (__half*)(smc + OFF_W2T);
    __half* W3Th   = (__half*)(smc + OFF_W3T);

    const unsigned sb = smem_u32(smc);
    const int t  = threadIdx.x;
    const int z  = blockIdx.x >> 1;
    const int hf = blockIdx.x & 1;

    // ---- mask sum -> fscale ----
    if (t < 32) {
        float m = mask[z * 64 + t] + mask[z * 64 + 32 + t];
        #pragma unroll
        for (int o = 16; o > 0; o >>= 1) m += __shfl_xor_sync(0xffffffff, m, o);
        if (t == 0) miscF[0] = rsqrtf(m);
    }

    // ---- stage weights (fp16 transposed) + W1 (fp32) + geo ----
    for (int i = t; i < 16384; i += THREADS) {
        int n = i >> 7, k = i & 127;
        W2Th[n * 136 + k] = __float2half_rn(W2[k * 128 + n]);
    }
    for (int i = t; i < 14336; i += THREADS) {
        int n = i >> 7, k = i & 127;
        W3Th[n * 136 + k] = __float2half_rn(W3[k * 112 + n]);
    }
    for (int i = t; i < 4096; i += THREADS) {
        int r_ = i >> 7, c_ = i & 127;
        W1S[r_ * 132 + c_] = W1[i];
    }
    for (int i = t; i < 192; i += THREADS) geoF[i] = geo[z * 192 + i];
    __syncthreads();

    // ---- stage scaled feats (fp32, stride 244) ----
    {
        const float fs = miscF[0];
        for (int i = t; i < 15360; i += THREADS) {
            int b = i / 240, j = i - b * 240;
            featsF[b * 244 + j] = rep[(size_t)(z * 64 + b) * 240 + j] * fs;
        }
    }
    __syncthreads();

    const int g     = t >> 7;          // group 0/1
    const int w     = (t >> 5) & 3;    // warp within group
    const int lane  = t & 31;
    const int q     = lane & 3;
    const int rowg  = lane >> 2;
    const int barid = 1 + g;

    char*    abp   = smc + (g ? OFF_AB1 : OFF_AB0);
    const unsigned Abase = sb + (g ? OFF_AB1 : OFF_AB0);
    const unsigned B2    = sb + OFF_W2T;
    const unsigned B3    = sb + OFF_W3T;

    const int prow = 32 * w + lane;    // this lane's prologue row (pair index)
    const int pb   = prow & 63;        // neighbor b of that row

    const float RS32  = 0.17677669529663687f;
    const float RS128 = 0.08838834764831843f;
    const float NORM0 = 0.125f;
    const float NORM1 = 0.10206207261596575f;
    const float NORM2 = 0.11180339887498948f;
    const float S3  = 1.7320508075688772f;
    const float S5  = 2.2360679774997896f;
    const float S15 = 3.872983346207417f;

    float cacc[32][4];   // fragment accumulators (GEMM1: [mt*16+nt], GEMM2: [mt*14+nt])

    #pragma unroll 1
    for (int it = 0; it < 8; it++) {
        const int base_a = hf * 32 + g * 16 + it * 2;
        const int a_glob = base_a + (w >> 1);

        // ---- per-row geometry: SH (regs) + 2-sparse cosine basis ----
        const float rx = geoF[a_glob * 3 + 0] - geoF[pb * 3 + 0];
        const float ry = geoF[a_glob * 3 + 1] - geoF[pb * 3 + 1];
        const float rz = geoF[a_glob * 3 + 2] - geoF[pb * 3 + 2];
        const float r2 = rx * rx + ry * ry + rz * rz;
        const float r  = sqrtf(fmaxf(r2, 1e-12f));
        const float nzf = (r2 > 1e-10f) ? 1.0f : 0.0f;
        const float inv = 1.0f / r;
        const float xh = rx * inv, yh = ry * inv, zh = rz * inv;
        float yv[8];
        yv[0] = S3 * xh * nzf;  yv[1] = S3 * yh * nzf;  yv[2] = S3 * zh * nzf;
        yv[3] = S15 * xh * yh * nzf;
        yv[4] = S15 * yh * zh * nzf;
        yv[5] = 0.5f * S5 * (3.0f * zh * zh - 1.0f) * nzf;
        yv[6] = S15 * xh * zh * nzf;
        yv[7] = 0.5f * S15 * (xh * xh - yh * yh) * nzf;

        const float u = r * 3.1f;         // r / (10/31)
        const int i0r = (int)floorf(u);
        const float d0 = u - (float)i0r;
        float sv, cv;
        __sincosf(1.5707963267948966f * d0, &sv, &cv);
        const float c0 = (i0r <= 31) ? cv : 0.0f;
        const float c1 = (i0r <= 30) ? sv : 0.0f;
        const int i0 = (i0r > 31) ? 31 : i0r;
        const int i1 = (i0r + 1 > 31) ? 31 : (i0r + 1);
        const float* w1a = W1S + i0 * 132;
        const float* w1b = W1S + i1 * 132;

        // ---- h1 prologue: this lane fills its own A-row (128 fp16) ----
        #pragma unroll 4
        for (int c8 = 0; c8 < 128; c8 += 8) {
            float4 A0 = *(const float4*)(w1a + c8);
            float4 A1 = *(const float4*)(w1a + c8 + 4);
            float4 Bb0 = *(const float4*)(w1b + c8);
            float4 Bb1 = *(const float4*)(w1b + c8 + 4);
            unsigned h0 = packh2(ssp_f((c0 * A0.x + c1 * Bb0.x) * RS32),
                                 ssp_f((c0 * A0.y + c1 * Bb0.y) * RS32));
            unsigned h1_ = packh2(ssp_f((c0 * A0.z + c1 * Bb0.z) * RS32),
                                  ssp_f((c0 * A0.w + c1 * Bb0.w) * RS32));
            unsigned h2_ = packh2(ssp_f((c0 * A1.x + c1 * Bb1.x) * RS32),
                                  ssp_f((c0 * A1.y + c1 * Bb1.y) * RS32));
            unsigned h3 = packh2(ssp_f((c0 * A1.z + c1 * Bb1.z) * RS32),
                                 ssp_f((c0 * A1.w + c1 * Bb1.w) * RS32));
            *(uint4*)(abp + prow * 272 + c8 * 2) = make_uint4(h0, h1_, h2_, h3);
        }
        __syncwarp();

        // ---- GEMM1: D1[128][128] = H1 @ W2 ----
        warp_gemm<16>(cacc, Abase, B2, w, lane);

        // ---- epilogue1: h2 = ssp(D1 * RS128) -> fp16 back into A rows ----
        #pragma unroll
        for (int mt = 0; mt < 2; mt++) {
            const int r1 = 32 * w + 16 * mt + rowg;
            const int r2_ = r1 + 8;
            #pragma unroll
            for (int nt = 0; nt < 16; nt++) {
                const int col = nt * 8 + 2 * q;
                float* cc = cacc[mt * 16 + nt];
                unsigned ha = packh2(ssp_f(cc[0] * RS128), ssp_f(cc[1] * RS128));
                unsigned hb = packh2(ssp_f(cc[2] * RS128), ssp_f(cc[3] * RS128));
                *(unsigned*)(abp + r1 * 272 + col * 2)  = ha;
                *(unsigned*)(abp + r2_ * 272 + col * 2) = hb;
            }
        }
        __syncwarp();

        // ---- GEMM2: D2[128][112] = H2 @ W3 ----
        warp_gemm<14>(cacc, Abase, B3, w, lane);

        // ---- contraction epilogue (fused): s = Σ_rows Σ_cols D2 * F ----
        float acc0 = 0.f, acc1 = 0.f, acc2 = 0.f;
        #pragma unroll
        for (int mt = 0; mt < 2; mt++) {
            const int src1 = 16 * mt + rowg;
            const int src2 = src1 + 8;
            float Y1[8], Y2[8];
            #pragma unroll
            for (int k = 0; k < 8; k++) {
                Y1[k] = __shfl_sync(0xffffffffu, yv[k], src1);
                Y2[k] = __shfl_sync(0xffffffffu, yv[k], src2);
            }
            const float* f1 = featsF + ((32 * w + src1) & 63) * 244;
            const float* f2 = featsF + ((32 * w + src2) & 63) * 244;
            // l=0 block: cols 0..63 (tiles 0..7)
            #pragma unroll
            for (int nt = 0; nt < 8; nt++) {
                const int n = nt * 8 + 2 * q;
                float* cc = cacc[mt * 14 + nt];
                acc0 += cc[0] * f1[n] + cc[1] * f1[n + 1]
                      + cc[2] * f2[n] + cc[3] * f2[n + 1];
            }
            // l=1 block: cols 64..95 (tiles 8..11), F = y . feats[64+3m ..]
            #pragma unroll
            for (int nt = 8; nt < 12; nt++) {
                const int m0 = nt * 8 + 2 * q - 64;
                const float* p1 = f1 + 64 + 3 * m0;
                const float* p2 = f2 + 64 + 3 * m0;
                float F10 = Y1[0] * p1[0] + Y1[1] * p1[1] + Y1[2] * p1[2];
                float F11 = Y1[0] * p1[3] + Y1[1] * p1[4] + Y1[2] * p1[5];
                float F20 = Y2[0] * p2[0] + Y2[1] * p2[1] + Y2[2] * p2[2];
                float F21 = Y2[0] * p2[3] + Y2[1] * p2[4] + Y2[2] * p2[5];
                float* cc = cacc[mt * 14 + nt];
                acc1 += cc[0] * F10 + cc[1] * F11 + cc[2] * F20 + cc[3] * F21;
            }
            // l=2 block: cols 96..111 (tiles 12..13), F = y . feats[160+5m ..]
            #pragma unroll
            for (int nt = 12; nt < 14; nt++) {
                const int m0 = nt * 8 + 2 * q - 96;
                const float* p1 = f1 + 160 + 5 * m0;
                const float* p2 = f2 + 160 + 5 * m0;
                float F10 = Y1[3] * p1[0] + Y1[4] * p1[1] + Y1[5] * p1[2]
                          + Y1[6] * p1[3] + Y1[7] * p1[4];
                float F11 = Y1[3] * p1[5] + Y1[4] * p1[6] + Y1[5] * p1[7]
                          + Y1[6] * p1[8] + Y1[7] * p1[9];
                float F20 = Y2[3] * p2[0] + Y2[4] * p2[1] + Y2[5] * p2[2]
                          + Y2[6] * p2[3] + Y2[7] * p2[4];
                float F21 = Y2[3] * p2[5] + Y2[4] * p2[6] + Y2[5] * p2[7]
                          + Y2[6] * p2[8] + Y2[7] * p2[9];
                float* cc = cacc[mt * 14 + nt];
                acc2 += cc[0] * F10 + cc[1] * F11 + cc[2] * F20 + cc[3] * F21;
            }
        }
        float sres = (acc0 * NORM0 + acc1 * NORM1 + acc2 * NORM2) * RS128;

        // ---- reduce: warp -> per-a sum across 2 warps ----
        #pragma unroll
        for (int o = 16; o > 0; o >>= 1)
            sres += __shfl_xor_sync(0xffffffff, sres, o);
        if (lane == 0) redF[g * 4 + w] = sres;
        barg(barid);
        {
            const int tg = t & 127;
            if (tg == 0 || tg == 64) {
                const int asub = tg >> 6;
                const int aa = base_a + asub;
                const float tot = redF[g * 4 + 2 * asub] + redF[g * 4 + 2 * asub + 1];
                const float bx = 5.0f * tot;
                const float sp = (fmaxf(bx, 0.0f)
                                  + __logf(1.0f + __expf(-fabsf(bx)))) * 0.2f;
                out[z * 64 + aa] = sp * mask[z * 64 + aa];
            }
        }
        barg(barid);
    }
}

extern "C" void kernel_launch(void* const* d_in, const int* in_sizes, int n_in,
                              void* d_out, int out_size)
{
    const float* rep  = (const float*)d_in[0];
    const float* geo  = (const float*)d_in[1];
    const float* mask = (const float*)d_in[2];
    const float* W1   = (const float*)d_in[3];
    const float* W2   = (const float*)d_in[4];
    const float* W3   = (const float*)d_in[5];
    float* out = (float*)d_out;

    cudaFuncSetAttribute(output_network_kernel,
                         cudaFuncAttributeMaxDynamicSharedMemorySize, SMEM_BYTES);
    output_network_kernel<<<GRIDX, THREADS, SMEM_BYTES>>>(rep, geo, mask, W1, W2, W3, out);
}

// round 8
// speedup vs baseline: 13.6752x; 1.1498x over previous
#include <cuda_runtime.h>
#include <cuda_fp16.h>
#include <math.h>

// OutputNetwork via mma.sync (HMMA), sm_103-safe PTX.
// 128 CTAs x 512 threads (16 warps). CTA = (z, a-half). Per iteration a CTA
// processes a 256-pair tile (4 a x 64 b); warp w owns rows 16w..16w+15 and is
// FULLY independent: h1 prologue -> GEMM1 (A via ldmatrix from private SMEM
// rows) -> in-register ssp + C->A fragment reuse -> GEMM2 -> fused SH
// contraction -> per-warp partial into a private SMEM slot. No cross-warp
// sync inside the loop; one __syncthreads + output pass at the end.

#define THREADS 512
#define GRIDX   128

// ---- dynamic SMEM byte offsets ----
#define OFF_AB    0         // h1 fp16 [256 rows][136] (272B rows)
#define OFF_W2T   69632     // W2^T fp16 [128 n][136]
#define OFF_W3T   104448    // W3^T fp16 [112 n][136]
#define OFF_W1S   134912    // W1 fp32 [32][132]
#define OFF_FEAT  151808    // feats fp32 [64][244]
#define OFF_GEO   214272    // fp32 [64][3]
#define OFF_PART  215040    // fp32 [8 iters][16 warps]
#define OFF_MISC  215552    // fscale
#define SMEM_BYTES 215616

__device__ __forceinline__ unsigned smem_u32(const void* p) {
    unsigned a;
    asm("{ .reg .u64 t; cvta.to.shared.u64 t, %1; cvt.u32.u64 %0, t; }" : "=r"(a) : "l"(p));
    return a;
}

__device__ __forceinline__ void ldm4(unsigned& r0, unsigned& r1, unsigned& r2, unsigned& r3,
                                     unsigned addr) {
    asm volatile("ldmatrix.sync.aligned.m8n8.x4.shared.b16 {%0, %1, %2, %3}, [%4];"
                 : "=r"(r0), "=r"(r1), "=r"(r2), "=r"(r3) : "r"(addr));
}

__device__ __forceinline__ void mma4(float* c, unsigned a0, unsigned a1, unsigned a2,
                                     unsigned a3, unsigned b0, unsigned b1) {
    asm volatile("mma.sync.aligned.m16n8k16.row.col.f32.f16.f16.f32 "
                 "{%0, %1, %2, %3}, {%4, %5, %6, %7}, {%8, %9}, {%0, %1, %2, %3};"
                 : "+f"(c[0]), "+f"(c[1]), "+f"(c[2]), "+f"(c[3])
                 : "r"(a0), "r"(a1), "r"(a2), "r"(a3), "r"(b0), "r"(b1));
}

// log1p(e) on (0,1], Chebyshev-derived degree-5, abs err ~1e-5
__device__ __forceinline__ float log1p_poly(float e) {
    return e * (0.99924f + e * (-0.49024f + e * (0.28528f +
               e * (-0.13159f + e * 0.0304522f))));
}

// (softplus(5x) - log 2) / 5, single MUFU (ex2)
__device__ __forceinline__ float ssp_f(float x) {
    float t = 5.0f * x;
    float e = __expf(-fabsf(t));
    return (fmaxf(t, 0.0f) + log1p_poly(e) - 0.69314718f) * 0.2f;
}

__device__ __forceinline__ unsigned packh2(float a, float b) {
    __half2 h = __floats2half2_rn(a, b);
    return reinterpret_cast<unsigned&>(h);
}

// GEMM with A (16 rows) from SMEM via ldmatrix: D[16][NT*8] += A[16][128] B^T
template<int NT>
__device__ __forceinline__ void gemm_smemA(float (*c)[4], unsigned Abase, unsigned Bbase,
                                           int lane) {
    #pragma unroll
    for (int i = 0; i < NT; i++) { c[i][0] = 0.f; c[i][1] = 0.f; c[i][2] = 0.f; c[i][3] = 0.f; }
    const int mi = lane >> 3, l7 = lane & 7;
    const int ar = (mi & 1) * 8 + l7;
    const int ac = (mi >> 1) * 8;
    const int bk = (mi & 1) * 8;
    const int bts = (mi >> 1);
    #pragma unroll
    for (int ks = 0; ks < 8; ks++) {
        unsigned a0, a1, a2, a3;
        ldm4(a0, a1, a2, a3, Abase + (unsigned)(ar * 272 + (ks * 16 + ac) * 2));
        #pragma unroll
        for (int p = 0; p < NT / 2; p++) {
            unsigned r0, r1, r2, r3;
            ldm4(r0, r1, r2, r3,
                 Bbase + (unsigned)(((2 * p + bts) * 8 + l7) * 272 + (ks * 16 + bk) * 2));
            mma4(c[2 * p],     a0, a1, a2, a3, r0, r1);
            mma4(c[2 * p + 1], a0, a1, a2, a3, r2, r3);
        }
    }
}

// GEMM with A from register fragments: D[16][NT*8] += Afrag B^T
template<int NT>
__device__ __forceinline__ void gemm_regA(float (*c)[4], const unsigned (*aff)[4],
                                          unsigned Bbase, int lane) {
    #pragma unroll
    for (int i = 0; i < NT; i++) { c[i][0] = 0.f; c[i][1] = 0.f; c[i][2] = 0.f; c[i][3] = 0.f; }
    const int mi = lane >> 3, l7 = lane & 7;
    const int bk = (mi & 1) * 8;
    const int bts = (mi >> 1);
    #pragma unroll
    for (int ks = 0; ks < 8; ks++) {
        #pragma unroll
        for (int p = 0; p < NT / 2; p++) {
            unsigned r0, r1, r2, r3;
            ldm4(r0, r1, r2, r3,
                 Bbase + (unsigned)(((2 * p + bts) * 8 + l7) * 272 + (ks * 16 + bk) * 2));
            mma4(c[2 * p],     aff[ks][0], aff[ks][1], aff[ks][2], aff[ks][3], r0, r1);
            mma4(c[2 * p + 1], aff[ks][0], aff[ks][1], aff[ks][2], aff[ks][3], r2, r3);
        }
    }
}

__global__ void __launch_bounds__(THREADS, 1)
output_network_kernel(const float* __restrict__ rep,
                      const float* __restrict__ geo,
                      const float* __restrict__ mask,
                      const float* __restrict__ W1,
                      const float* __restrict__ W2,
                      const float* __restrict__ W3,
                      float* __restrict__ out)
{
    extern __shared__ char smc[];
    float*  W1S    = (float*)(smc + OFF_W1S);
    float*  featsF = (float*)(smc + OFF_FEAT);
    float*  geoF   = (float*)(smc + OFF_GEO);
    float*  partF  = (float*)(smc + OFF_PART);
    float*  miscF  = (float*)(smc + OFF_MISC);
    __half* W2Th   = (__half*)(smc + OFF_W2T);
    __half* W3Th   = (__half*)(smc + OFF_W3T);

    const unsigned sb = smem_u32(smc);
    const int t  = threadIdx.x;
    const int z  = blockIdx.x >> 1;
    const int hf = blockIdx.x & 1;

    // ---- mask sum -> fscale ----
    if (t < 32) {
        float m = mask[z * 64 + t] + mask[z * 64 + 32 + t];
        #pragma unroll
        for (int o = 16; o > 0; o >>= 1) m += __shfl_xor_sync(0xffffffff, m, o);
        if (t == 0) miscF[0] = rsqrtf(m);
    }

    // ---- stage weights + geo ----
    for (int i = t; i < 16384; i += THREADS) {
        int n = i >> 7, k = i & 127;
        W2Th[n * 136 + k] = __float2half_rn(W2[k * 128 + n]);
    }
    for (int i = t; i < 14336; i += THREADS) {
        int n = i >> 7, k = i & 127;
        W3Th[n * 136 + k] = __float2half_rn(W3[k * 112 + n]);
    }
    for (int i = t; i < 4096; i += THREADS) {
        int r_ = i >> 7, c_ = i & 127;
        W1S[r_ * 132 + c_] = W1[i];
    }
    for (int i = t; i < 192; i += THREADS) geoF[i] = geo[z * 192 + i];
    __syncthreads();

    // ---- stage scaled feats (fp32, row stride 244) ----
    {
        const float fs = miscF[0];
        for (int i = t; i < 15360; i += THREADS) {
            int b = i / 240, j = i - b * 240;
            featsF[b * 244 + j] = rep[(size_t)(z * 64 + b) * 240 + j] * fs;
        }
    }
    __syncthreads();

    const int w    = t >> 5;        // warp 0..15
    const int lane = t & 31;
    const int q    = lane & 3;
    const int rowg = lane >> 2;

    const unsigned Abase = sb + OFF_AB + (unsigned)(16 * w * 272);
    const unsigned B2    = sb + OFF_W2T;
    const unsigned B3    = sb + OFF_W3T;
    char* abp = smc + OFF_AB + 16 * w * 272;

    // prologue assignment: 2 lanes per row
    const int prow_loc = lane >> 1;          // row within 16-row band
    const int pcol0    = (lane & 1) * 64;    // column half
    const int pb       = 16 * (w & 3) + prow_loc;   // neighbor b of prologue row

    // contraction rows (fixed across iters)
    const int b1 = 16 * (w & 3) + rowg;      // fragment row rowg
    const int b2 = b1 + 8;                   // fragment row rowg+8
    const float* f1 = featsF + b1 * 244;
    const float* f2 = featsF + b2 * 244;

    const float RS32  = 0.17677669529663687f;
    const float RS128 = 0.08838834764831843f;
    const float NORM0 = 0.125f;
    const float NORM1 = 0.10206207261596575f;
    const float NORM2 = 0.11180339887498948f;
    const float S3  = 1.7320508075688772f;
    const float S5  = 2.2360679774997896f;
    const float S15 = 3.872983346207417f;

    float    cacc[16][4];
    unsigned aff[8][4];

    #pragma unroll 1
    for (int it = 0; it < 8; it++) {
        const int a_glob = hf * 32 + it * 4 + (w >> 2);

        // ---- per-row geometry: SH (regs) + 2-sparse cosine basis ----
        const float rx = geoF[a_glob * 3 + 0] - geoF[pb * 3 + 0];
        const float ry = geoF[a_glob * 3 + 1] - geoF[pb * 3 + 1];
        const float rz = geoF[a_glob * 3 + 2] - geoF[pb * 3 + 2];
        const float r2 = rx * rx + ry * ry + rz * rz;
        const float r  = sqrtf(fmaxf(r2, 1e-12f));
        const float nzf = (r2 > 1e-10f) ? 1.0f : 0.0f;
        const float inv = 1.0f / r;
        const float xh = rx * inv, yh = ry * inv, zh = rz * inv;
        float yv[8];
        yv[0] = S3 * xh * nzf;  yv[1] = S3 * yh * nzf;  yv[2] = S3 * zh * nzf;
        yv[3] = S15 * xh * yh * nzf;
        yv[4] = S15 * yh * zh * nzf;
        yv[5] = 0.5f * S5 * (3.0f * zh * zh - 1.0f) * nzf;
        yv[6] = S15 * xh * zh * nzf;
        yv[7] = 0.5f * S15 * (xh * xh - yh * yh) * nzf;

        const float u = r * 3.1f;           // r / (10/31)
        const int i0r = (int)floorf(u);
        const float d0 = u - (float)i0r;
        float sv, cv;
        __sincosf(1.5707963267948966f * d0, &sv, &cv);
        const float c0 = (i0r <= 31) ? cv : 0.0f;
        const float c1 = (i0r <= 30) ? sv : 0.0f;
        const int i0 = (i0r > 31) ? 31 : i0r;
        const int i1 = (i0r + 1 > 31) ? 31 : (i0r + 1);
        const float* w1a = W1S + i0 * 132 + pcol0;
        const float* w1b = W1S + i1 * 132 + pcol0;

        // ---- h1 prologue: 2 lanes fill this row's 64-col half each ----
        #pragma unroll 4
        for (int c8 = 0; c8 < 64; c8 += 8) {
            float4 A0 = *(const float4*)(w1a + c8);
            float4 A1 = *(const float4*)(w1a + c8 + 4);
            float4 Bb0 = *(const float4*)(w1b + c8);
            float4 Bb1 = *(const float4*)(w1b + c8 + 4);
            unsigned h0 = packh2(ssp_f((c0 * A0.x + c1 * Bb0.x) * RS32),
                                 ssp_f((c0 * A0.y + c1 * Bb0.y) * RS32));
            unsigned h1_ = packh2(ssp_f((c0 * A0.z + c1 * Bb0.z) * RS32),
                                  ssp_f((c0 * A0.w + c1 * Bb0.w) * RS32));
            unsigned h2_ = packh2(ssp_f((c0 * A1.x + c1 * Bb1.x) * RS32),
                                  ssp_f((c0 * A1.y + c1 * Bb1.y) * RS32));
            unsigned h3 = packh2(ssp_f((c0 * A1.z + c1 * Bb1.z) * RS32),
                                 ssp_f((c0 * A1.w + c1 * Bb1.w) * RS32));
            *(uint4*)(abp + prow_loc * 272 + (pcol0 + c8) * 2) = make_uint4(h0, h1_, h2_, h3);
        }
        __syncwarp();

        // ---- GEMM1: D1[16][128] = H1 @ W2 ----
        gemm_smemA<16>(cacc, Abase, B2, lane);

        // ---- in-register epilogue1: C fragments -> ssp -> A fragments ----
        #pragma unroll
        for (int j = 0; j < 8; j++) {
            aff[j][0] = packh2(ssp_f(cacc[2 * j][0] * RS128),
                               ssp_f(cacc[2 * j][1] * RS128));
            aff[j][1] = packh2(ssp_f(cacc[2 * j][2] * RS128),
                               ssp_f(cacc[2 * j][3] * RS128));
            aff[j][2] = packh2(ssp_f(cacc[2 * j + 1][0] * RS128),
                               ssp_f(cacc[2 * j + 1][1] * RS128));
            aff[j][3] = packh2(ssp_f(cacc[2 * j + 1][2] * RS128),
                               ssp_f(cacc[2 * j + 1][3] * RS128));
        }

        // ---- GEMM2: D2[16][112] = H2 @ W3 ----
        gemm_regA<14>(cacc, aff, B3, lane);

        // ---- fused SH contraction ----
        float Y1[8], Y2[8];
        #pragma unroll
        for (int k = 0; k < 8; k++) {
            Y1[k] = __shfl_sync(0xffffffffu, yv[k], 2 * rowg);
            Y2[k] = __shfl_sync(0xffffffffu, yv[k], 2 * rowg + 16);
        }
        float acc0 = 0.f, acc1 = 0.f, acc2 = 0.f;
        // l=0: cols 0..63 (tiles 0..7)
        #pragma unroll
        for (int nt = 0; nt < 8; nt++) {
            const int n = nt * 8 + 2 * q;
            float* cc = cacc[nt];
            acc0 += cc[0] * f1[n] + cc[1] * f1[n + 1]
                  + cc[2] * f2[n] + cc[3] * f2[n + 1];
        }
        // l=1: cols 64..95 (tiles 8..11)
        #pragma unroll
        for (int nt = 8; nt < 12; nt++) {
            const int m0 = nt * 8 + 2 * q - 64;
            const float* p1 = f1 + 64 + 3 * m0;
            const float* p2 = f2 + 64 + 3 * m0;
            float F10 = Y1[0] * p1[0] + Y1[1] * p1[1] + Y1[2] * p1[2];
            float F11 = Y1[0] * p1[3] + Y1[1] * p1[4] + Y1[2] * p1[5];
            float F20 = Y2[0] * p2[0] + Y2[1] * p2[1] + Y2[2] * p2[2];
            float F21 = Y2[0] * p2[3] + Y2[1] * p2[4] + Y2[2] * p2[5];
            float* cc = cacc[nt];
            acc1 += cc[0] * F10 + cc[1] * F11 + cc[2] * F20 + cc[3] * F21;
        }
        // l=2: cols 96..111 (tiles 12..13)
        #pragma unroll
        for (int nt = 12; nt < 14; nt++) {
            const int m0 = nt * 8 + 2 * q - 96;
            const float* p1 = f1 + 160 + 5 * m0;
            const float* p2 = f2 + 160 + 5 * m0;
            float F10 = Y1[3] * p1[0] + Y1[4] * p1[1] + Y1[5] * p1[2]
                      + Y1[6] * p1[3] + Y1[7] * p1[4];
            float F11 = Y1[3] * p1[5] + Y1[4] * p1[6] + Y1[5] * p1[7]
                      + Y1[6] * p1[8] + Y1[7] * p1[9];
            float F20 = Y2[3] * p2[0] + Y2[4] * p2[1] + Y2[5] * p2[2]
                      + Y2[6] * p2[3] + Y2[7] * p2[4];
            float F21 = Y2[3] * p2[5] + Y2[4] * p2[6] + Y2[5] * p2[7]
                      + Y2[6] * p2[8] + Y2[7] * p2[9];
            float* cc = cacc[nt];
            acc2 += cc[0] * F10 + cc[1] * F11 + cc[2] * F20 + cc[3] * F21;
        }
        float sres = (acc0 * NORM0 + acc1 * NORM1 + acc2 * NORM2) * RS128;

        // ---- warp reduce -> private partial slot (no cross-warp sync) ----
        #pragma unroll
        for (int o = 16; o > 0; o >>= 1)
            sres += __shfl_xor_sync(0xffffffff, sres, o);
        if (lane == 0) partF[it * 16 + w] = sres;
    }

    // ---- final output pass ----
    __syncthreads();
    if (t < 32) {
        const int it = t >> 2;
        const int al = t & 3;
        const float tot = partF[it * 16 + 4 * al + 0] + partF[it * 16 + 4 * al + 1]
                        + partF[it * 16 + 4 * al + 2] + partF[it * 16 + 4 * al + 3];
        const int aa = hf * 32 + it * 4 + al;
        const float bx = 5.0f * tot;
        const float e  = __expf(-fabsf(bx));
        const float sp = (fmaxf(bx, 0.0f) + log1p_poly(e)) * 0.2f;
        out[z * 64 + aa] = sp * mask[z * 64 + aa];
    }
}

extern "C" void kernel_launch(void* const* d_in, const int* in_sizes, int n_in,
                              void* d_out, int out_size)
{
    const float* rep  = (const float*)d_in[0];
    const float* geo  = (const float*)d_in[1];
    const float* mask = (const float*)d_in[2];
    const float* W1   = (const float*)d_in[3];
    const float* W2   = (const float*)d_in[4];
    const float* W3   = (const float*)d_in[5];
    float* out = (float*)d_out;

    cudaFuncSetAttribute(output_network_kernel,
                         cudaFuncAttributeMaxDynamicSharedMemorySize, SMEM_BYTES);
    output_network_kernel<<<GRIDX, THREADS, SMEM_BYTES>>>(rep, geo, mask, W1, W2, W3, out);
}

// round 11
// speedup vs baseline: 20.8717x; 1.5262x over previous
#include <cuda_runtime.h>
#include <math.h>

// OutputNetwork via radial tabulation + SEGMENT-CONFINED quintic interpolation.
// R(r) is analytic between kinks at r = m*step (step = 10/31, cosine-window
// edges, C0 joins). Grid h = step/12 puts kinks on nodes; the 6-tap Lagrange
// stencil is clamped to stay inside one 12-interval segment, so it never
// crosses a kink -> spectral accuracy. Support ends exactly at node 384.

#define NR      385              // nodes r = n*h, n = 0..384 (r in [0, 32*step])
#define THREADS 512
#define GRIDX   128

// ---- main-kernel SMEM layout (float offsets) ----
#define OFF_TAB   0              // T [385][112] = 43120
#define OFF_REC   43120          // 16 w x 32 p x 24 f = 12288
#define OFF_GEO   55408          // geo [64][3]
#define OFF_PART  55600          // partials [16 w][32]
#define OFF_MISC  56112          // fscale
#define SMEM_FLOATS 56116
#define SMEM_BYTES  (SMEM_FLOATS * 4)

// ---- build-kernel SMEM (floats) ----
#define BOFF_W2   0
#define BOFF_W3   16384
#define BOFF_H1   30720
#define BOFF_H2   31232
#define BSMEM_FLOATS 31744
#define BSMEM_BYTES  (BSMEM_FLOATS * 4)

__device__ float g_table[NR * 112];

__device__ __forceinline__ float ssp_precise(float x) {
    float bx = 5.0f * x;
    return (fmaxf(bx, 0.0f) + log1pf(expf(-fabsf(bx))) - 0.69314718055994531f) * 0.2f;
}

// ============================ kernel 1: build table ============================
__global__ void __launch_bounds__(512, 1)
build_table_kernel(const float* __restrict__ W1,
                   const float* __restrict__ W2,
                   const float* __restrict__ W3)
{
    extern __shared__ float bs[];
    float* W2s = bs + BOFF_W2;
    float* W3s = bs + BOFF_W3;
    float* h1s = bs + BOFF_H1;
    float* h2s = bs + BOFF_H2;

    const int t  = threadIdx.x;
    const int rg = t >> 7;
    const int tl = t & 127;

    for (int i = t; i < 16384; i += 512) W2s[i] = W2[i];
    for (int i = t; i < 14336; i += 512) W3s[i] = W3[i];
    __syncthreads();

    const int row = blockIdx.x * 4 + rg;
    if (row >= NR) return;
    const float r = (float)row / 37.2f;   // node r; u = r*37.2 maps back to row

    const float RS32  = 0.17677669529663687f;
    const float RS128 = 0.08838834764831843f;

    // h1 = ssp( basis(r) @ W1 / sqrt(32) )
    float pre = 0.0f;
    #pragma unroll
    for (int kb = 0; kb < 32; kb++) {
        float d = r * 3.1f - (float)kb;
        float wv = (fabsf(d) < 1.0f) ? cosf(1.5707963267948966f * d) : 0.0f;
        pre += wv * W1[kb * 128 + tl];
    }
    h1s[rg * 128 + tl] = ssp_precise(pre * RS32);
    __syncthreads();

    float a2 = 0.0f;
    #pragma unroll 8
    for (int k = 0; k < 128; k++) a2 += h1s[rg * 128 + k] * W2s[k * 128 + tl];
    h2s[rg * 128 + tl] = ssp_precise(a2 * RS128);
    __syncthreads();

    if (tl < 112) {
        float a3 = 0.0f;
        #pragma unroll 8
        for (int k = 0; k < 128; k++) a3 += h2s[rg * 128 + k] * W3s[k * 112 + tl];
        const float norm = (tl < 64) ? 0.125f
                         : (tl < 96) ? 0.10206207261596575f
                                     : 0.11180339887498948f;
        g_table[row * 112 + tl] = a3 * RS128 * norm;
    }
}

// ============================ kernel 2: main ============================
__global__ void __launch_bounds__(THREADS, 1)
output_network_kernel(const float* __restrict__ rep,
                      const float* __restrict__ geo,
                      const float* __restrict__ mask,
                      float* __restrict__ out)
{
    extern __shared__ float s[];
    float* tabS  = s + OFF_TAB;
    float* recS  = s + OFF_REC;
    float* geoS  = s + OFF_GEO;
    float* partS = s + OFF_PART;
    float* miscF = s + OFF_MISC;

    const int t  = threadIdx.x;
    const int z  = blockIdx.x >> 1;
    const int hf = blockIdx.x & 1;

    if (t < 32) {
        float m = mask[z * 64 + t] + mask[z * 64 + 32 + t];
        #pragma unroll
        for (int o = 16; o > 0; o >>= 1) m += __shfl_xor_sync(0xffffffff, m, o);
        if (t == 0) miscF[0] = rsqrtf(m);
    }

    {
        // NR*112 = 43120 floats = 10780 float4
        const float4* gt = (const float4*)g_table;
        float4* st = (float4*)tabS;
        #pragma unroll 4
        for (int i = t; i < (NR * 112) / 4; i += THREADS) st[i] = gt[i];
    }
    for (int i = t; i < 192; i += THREADS) geoS[i] = geo[z * 192 + i];
    __syncthreads();

    const float fscale = miscF[0];
    const int w    = t >> 5;
    const int lane = t & 31;

    // lane -> j assignment (4 j's each; lanes 28..31 inactive)
    const int ln_ = (lane < 28) ? lane : 27;
    const int j0 = 4 * ln_;
    int yo, fo0, fstr;
    if (j0 < 64)      { yo = 0;  fo0 = j0;                  fstr = 1; }
    else if (j0 < 96) { yo = 5;  fo0 = 64 + 3 * (j0 - 64);  fstr = 3; }
    else              { yo = 10; fo0 = 160 + 5 * (j0 - 96); fstr = 5; }
    const float act = (lane < 28) ? 1.0f : 0.0f;

    float* recW = recS + w * 768;   // 32 pairs x 24 floats

    const float S3  = 1.7320508075688772f;
    const float S5  = 2.2360679774997896f;
    const float S15 = 3.872983346207417f;

    #pragma unroll 1
    for (int chunk = 0; chunk < 4; chunk++) {
        // ---- precompute: lane = pair p (8 a x 4 b) ----
        {
            const int p  = lane;
            const int al = p & 7;
            const int bl = p >> 3;
            const int a  = hf * 32 + chunk * 8 + al;
            const int b  = 4 * w + bl;
            const float rx = geoS[a * 3 + 0] - geoS[b * 3 + 0];
            const float ry = geoS[a * 3 + 1] - geoS[b * 3 + 1];
            const float rz = geoS[a * 3 + 2] - geoS[b * 3 + 2];
            const float r2 = rx * rx + ry * ry + rz * rz;
            const float r  = sqrtf(fmaxf(r2, 1e-12f));
            const float nzf = (r2 > 1e-10f) ? fscale : 0.0f;
            const float inv = 1.0f / r;
            const float xh = rx * inv, yh = ry * inv, zh = rz * inv;

            float* rec = recW + p * 24;
            rec[0]  = fscale;
            rec[1]  = 0.0f; rec[2] = 0.0f; rec[3] = 0.0f; rec[4] = 0.0f;
            rec[5]  = S3 * xh * nzf;
            rec[6]  = S3 * yh * nzf;
            rec[7]  = S3 * zh * nzf;
            rec[8]  = 0.0f; rec[9] = 0.0f;
            rec[10] = S15 * xh * yh * nzf;
            rec[11] = S15 * yh * zh * nzf;
            rec[12] = 0.5f * S5 * (3.0f * zh * zh - 1.0f) * nzf;
            rec[13] = S15 * xh * zh * nzf;
            rec[14] = 0.5f * S15 * (xh * xh - yh * yh) * nzf;
            rec[15] = 0.0f;

            // segment-confined quintic stencil
            float u = r * 37.2f;                       // node units
            const float sup = (u < 384.0f) ? 1.0f : 0.0f;  // R==0 beyond support
            u = fminf(u, 383.99f);
            int sg = (int)(u * 0.0833333333f);         // segment 0..31
            sg = (sg > 31) ? 31 : sg;
            float xi = u - 12.0f * (float)sg;          // [0,12)
            int   nl = (int)xi;                        // local node 0..11
            int   s0 = nl - 2;
            s0 = (s0 < 0) ? 0 : ((s0 > 7) ? 7 : s0);
            const float tt = xi - (float)s0;           // position in stencil [0,6)
            const int gs = 12 * sg + s0;               // global stencil start (<=379)

            // general-position 6-pt Lagrange weights (prefix/suffix products)
            const float p0 = tt,       p1 = tt - 1.0f, p2 = tt - 2.0f;
            const float p3 = tt - 3.0f, p4 = tt - 4.0f, p5 = tt - 5.0f;
            const float pr2 = p0 * p1, pr3 = pr2 * p2, pr4 = pr3 * p3, pr5 = pr4 * p4;
            const float sf3 = p4 * p5, sf2 = p3 * sf3, sf1 = p2 * sf2, sf0 = p1 * sf1;
            rec[16] = sup * (-8.3333333333e-3f) * sf0;          // /(-120)
            rec[17] = sup * ( 4.1666666667e-2f) * p0 * sf1;     // /24
            rec[18] = sup * (-8.3333333333e-2f) * pr2 * sf2;    // /(-12)
            rec[19] = sup * ( 8.3333333333e-2f) * pr3 * sf3;    // /12
            rec[20] = sup * (-4.1666666667e-2f) * pr4 * p5;     // /(-24)
            rec[21] = sup * ( 8.3333333333e-3f) * pr5;          // /120
            ((int*)rec)[22] = gs;
        }
        __syncwarp();

        float acc[8];
        #pragma unroll
        for (int al = 0; al < 8; al++) acc[al] = 0.0f;

        #pragma unroll 1
        for (int bl = 0; bl < 4; bl++) {
            const float* fbase = rep + (size_t)(z * 64 + 4 * w + bl) * 240 + fo0;
            float fr[4][5];
            #pragma unroll
            for (int jj = 0; jj < 4; jj++)
                #pragma unroll
                for (int k = 0; k < 5; k++)
                    fr[jj][k] = __ldg(fbase + fstr * jj + k);

            #pragma unroll
            for (int al = 0; al < 8; al++) {
                const float* rec = recW + (bl * 8 + al) * 24;
                const float4 wA = *(const float4*)(rec + 16);  // w0..w3
                const float w4  = rec[20];
                const float w5  = rec[21];
                const int   gs  = ((const int*)rec)[22];
                const float ye0 = rec[yo + 0];
                const float ye1 = rec[yo + 1];
                const float ye2 = rec[yo + 2];
                const float ye3 = rec[yo + 3];
                const float ye4 = rec[yo + 4];

                const float* tb = tabS + gs * 112 + j0;
                const float4 t0 = *(const float4*)(tb);
                const float4 t1 = *(const float4*)(tb + 112);
                const float4 t2 = *(const float4*)(tb + 224);
                const float4 t3 = *(const float4*)(tb + 336);
                const float4 t4 = *(const float4*)(tb + 448);
                const float4 t5 = *(const float4*)(tb + 560);

                float R0 = wA.x * t0.x; R0 = fmaf(wA.y, t1.x, R0);
                R0 = fmaf(wA.z, t2.x, R0); R0 = fmaf(wA.w, t3.x, R0);
                R0 = fmaf(w4, t4.x, R0);  R0 = fmaf(w5, t5.x, R0);
                float R1 = wA.x * t0.y; R1 = fmaf(wA.y, t1.y, R1);
                R1 = fmaf(wA.z, t2.y, R1); R1 = fmaf(wA.w, t3.y, R1);
                R1 = fmaf(w4, t4.y, R1);  R1 = fmaf(w5, t5.y, R1);
                float R2 = wA.x * t0.z; R2 = fmaf(wA.y, t1.z, R2);
                R2 = fmaf(wA.z, t2.z, R2); R2 = fmaf(wA.w, t3.z, R2);
                R2 = fmaf(w4, t4.z, R2);  R2 = fmaf(w5, t5.z, R2);
                float R3 = wA.x * t0.w; R3 = fmaf(wA.y, t1.w, R3);
                R3 = fmaf(wA.z, t2.w, R3); R3 = fmaf(wA.w, t3.w, R3);
                R3 = fmaf(w4, t4.w, R3);  R3 = fmaf(w5, t5.w, R3);

                float F0 = ye0 * fr[0][0]; F0 = fmaf(ye1, fr[0][1], F0);
                F0 = fmaf(ye2, fr[0][2], F0); F0 = fmaf(ye3, fr[0][3], F0);
                F0 = fmaf(ye4, fr[0][4], F0);
                float F1 = ye0 * fr[1][0]; F1 = fmaf(ye1, fr[1][1], F1);
                F1 = fmaf(ye2, fr[1][2], F1); F1 = fmaf(ye3, fr[1][3], F1);
                F1 = fmaf(ye4, fr[1][4], F1);
                float F2 = ye0 * fr[2][0]; F2 = fmaf(ye1, fr[2][1], F2);
                F2 = fmaf(ye2, fr[2][2], F2); F2 = fmaf(ye3, fr[2][3], F2);
                F2 = fmaf(ye4, fr[2][4], F2);
                float F3 = ye0 * fr[3][0]; F3 = fmaf(ye1, fr[3][1], F3);
                F3 = fmaf(ye2, fr[3][2], F3); F3 = fmaf(ye3, fr[3][3], F3);
                F3 = fmaf(ye4, fr[3][4], F3);

                float ct = R0 * F0;
                ct = fmaf(R1, F1, ct);
                ct = fmaf(R2, F2, ct);
                ct = fmaf(R3, F3, ct);
                acc[al] = fmaf(act, ct, acc[al]);
            }
        }

        #pragma unroll
        for (int al = 0; al < 8; al++) {
            float v = acc[al];
            #pragma unroll
            for (int o = 16; o > 0; o >>= 1)
                v += __shfl_xor_sync(0xffffffff, v, o);
            if (lane == al) partS[w * 32 + chunk * 8 + al] = v;
        }
    }

    __syncthreads();
    if (t < 32) {
        float tot = 0.0f;
        #pragma unroll
        for (int ww = 0; ww < 16; ww++) tot += partS[ww * 32 + t];
        const int aa = hf * 32 + t;
        const float bx = 5.0f * tot;
        const float sp = (fmaxf(bx, 0.0f) + log1pf(expf(-fabsf(bx)))) * 0.2f;
        out[z * 64 + aa] = sp * mask[z * 64 + aa];
    }
}

extern "C" void kernel_launch(void* const* d_in, const int* in_sizes, int n_in,
                              void* d_out, int out_size)
{
    const float* rep  = (const float*)d_in[0];
    const float* geo  = (const float*)d_in[1];
    const float* mask = (const float*)d_in[2];
    const float* W1   = (const float*)d_in[3];
    const float* W2   = (const float*)d_in[4];
    const float* W3   = (const float*)d_in[5];
    float* out = (float*)d_out;

    cudaFuncSetAttribute(build_table_kernel,
                         cudaFuncAttributeMaxDynamicSharedMemorySize, BSMEM_BYTES);
    cudaFuncSetAttribute(output_network_kernel,
                         cudaFuncAttributeMaxDynamicSharedMemorySize, SMEM_BYTES);

    build_table_kernel<<<(NR + 3) / 4, 512, BSMEM_BYTES>>>(W1, W2, W3);
    output_network_kernel<<<GRIDX, THREADS, SMEM_BYTES>>>(rep, geo, mask, out);
}

// round 12
// speedup vs baseline: 21.1517x; 1.0134x over previous
#include <cuda_runtime.h>
#include <cuda_fp16.h>
#include <math.h>

// OutputNetwork via radial tabulation, segment-confined quintic interpolation,
// l=0 pre-contraction (G0) and fp16 l>=1 table.
//   build kernel: T[385][112] on grid h=step/12 (kinks on nodes) ->
//                 g_tab0[385][64] fp32 (l=0 cols), g_tab16[385][48] fp16.
//   main kernel:  per-CTA G0[row][b] = sum_j T0[row][j]*feats[b][j] prologue,
//                 then per-pair: 6-tap in-segment quintic of (G0 | fp16 table)
//                 fused with SH contraction. 2 pairs per warp-iteration.

#define NRR     385
#define THREADS 512
#define GRIDX   128

// ---- main-kernel SMEM (float offsets) ----
#define OFF_G0    0            // G0 [385][65] fp32 = 25025 (+1 pad)
#define OFF_TH    25026        // fp16 [385][48] = 9240 u32
#define OFF_REC   34268        // recs 16w x 32p x 24f = 12288 (FL0 [64][68] during prologue)
#define OFF_GEO   46556        // [64][3]
#define OFF_PART  46748        // [16][32]
#define OFF_MISC  47260
#define SMEM_FLOATS 47264
#define SMEM_BYTES  (SMEM_FLOATS * 4)

// ---- build-kernel SMEM ----
#define BOFF_W2   0
#define BOFF_W3   16384
#define BOFF_H1   30720
#define BOFF_H2   31232
#define BSMEM_FLOATS 31744
#define BSMEM_BYTES  (BSMEM_FLOATS * 4)

__device__ float  g_tab0[NRR * 64];
__device__ __half g_tab16[NRR * 48];

__device__ __forceinline__ float ssp_precise(float x) {
    float bx = 5.0f * x;
    return (fmaxf(bx, 0.0f) + log1pf(expf(-fabsf(bx))) - 0.69314718055994531f) * 0.2f;
}

// ============================ kernel 1: build table ============================
__global__ void __launch_bounds__(512, 1)
build_table_kernel(const float* __restrict__ W1,
                   const float* __restrict__ W2,
                   const float* __restrict__ W3)
{
    extern __shared__ float bs[];
    float* W2s = bs + BOFF_W2;
    float* W3s = bs + BOFF_W3;
    float* h1s = bs + BOFF_H1;
    float* h2s = bs + BOFF_H2;

    const int t  = threadIdx.x;
    const int rg = t >> 7;
    const int tl = t & 127;

    for (int i = t; i < 16384; i += 512) W2s[i] = W2[i];
    for (int i = t; i < 14336; i += 512) W3s[i] = W3[i];
    __syncthreads();

    const float RS32  = 0.17677669529663687f;
    const float RS128 = 0.08838834764831843f;

    #pragma unroll 1
    for (int qi = 0; qi < 2; qi++) {
        const int row = blockIdx.x * 8 + qi * 4 + rg;
        const bool live = (row < NRR);
        const float r = (float)row / 37.2f;   // node radius

        float pre = 0.0f;
        #pragma unroll
        for (int kb = 0; kb < 32; kb++) {
            float d = r * 3.1f - (float)kb;
            float wv = (fabsf(d) < 1.0f) ? cosf(1.5707963267948966f * d) : 0.0f;
            pre += wv * W1[kb * 128 + tl];
        }
        h1s[rg * 128 + tl] = ssp_precise(pre * RS32);
        __syncthreads();

        float a2 = 0.0f;
        #pragma unroll 8
        for (int k = 0; k < 128; k++) a2 += h1s[rg * 128 + k] * W2s[k * 128 + tl];
        h2s[rg * 128 + tl] = ssp_precise(a2 * RS128);
        __syncthreads();

        if (live && tl < 112) {
            float a3 = 0.0f;
            #pragma unroll 8
            for (int k = 0; k < 128; k++) a3 += h2s[rg * 128 + k] * W3s[k * 112 + tl];
            const float norm = (tl < 64) ? 0.125f
                             : (tl < 96) ? 0.10206207261596575f
                                         : 0.11180339887498948f;
            const float val = a3 * RS128 * norm;
            if (tl < 64) g_tab0[row * 64 + tl] = val;
            else         g_tab16[row * 48 + (tl - 64)] = __float2half_rn(val);
        }
        __syncthreads();
    }
}

// ============================ kernel 2: main ============================
__global__ void __launch_bounds__(THREADS, 1)
output_network_kernel(const float* __restrict__ rep,
                      const float* __restrict__ geo,
                      const float* __restrict__ mask,
                      float* __restrict__ out)
{
    extern __shared__ float s[];
    float*    G0S   = s + OFF_G0;
    unsigned* THs   = (unsigned*)(s + OFF_TH);
    float*    recS  = s + OFF_REC;
    float*    FL0   = s + OFF_REC;      // alias: used only before recs exist
    float*    geoS  = s + OFF_GEO;
    float*    partS = s + OFF_PART;
    float*    miscF = s + OFF_MISC;

    const int t  = threadIdx.x;
    const int z  = blockIdx.x >> 1;
    const int hf = blockIdx.x & 1;

    // ---- fscale ----
    if (t < 32) {
        float m = mask[z * 64 + t] + mask[z * 64 + 32 + t];
        #pragma unroll
        for (int o = 16; o > 0; o >>= 1) m += __shfl_xor_sync(0xffffffff, m, o);
        if (t == 0) miscF[0] = rsqrtf(m);
    }
    __syncthreads();
    const float fs = miscF[0];

    // ---- stage fp16 l>=1 table, scaled l=0 feats, geo ----
    {
        const unsigned* g16 = (const unsigned*)g_tab16;
        for (int i = t; i < 9240; i += THREADS) THs[i] = g16[i];
    }
    for (int i = t; i < 4096; i += THREADS) {
        int b = i >> 6, j = i & 63;
        FL0[b * 68 + j] = rep[(size_t)(z * 64 + b) * 240 + j] * fs;
    }
    for (int i = t; i < 192; i += THREADS) geoS[i] = geo[z * 192 + i];
    __syncthreads();

    // ---- G0 prologue: thread = table row ----
    if (t < NRR) {
        float4 T4[16];
        const float4* trow = (const float4*)(g_tab0 + t * 64);
        #pragma unroll
        for (int k = 0; k < 16; k++) T4[k] = trow[k];
        #pragma unroll 1
        for (int b = 0; b < 64; b++) {
            const float4* fb4 = (const float4*)(FL0 + b * 68);
            float acc = 0.0f;
            #pragma unroll
            for (int k = 0; k < 16; k++) {
                float4 fv = fb4[k];
                acc = fmaf(T4[k].x, fv.x, acc);
                acc = fmaf(T4[k].y, fv.y, acc);
                acc = fmaf(T4[k].z, fv.z, acc);
                acc = fmaf(T4[k].w, fv.w, acc);
            }
            G0S[t * 65 + b] = acc;
        }
    }
    __syncthreads();   // FL0 area becomes rec area after this point

    const int w    = t >> 5;
    const int lane = t & 31;
    const int hw   = lane >> 4;       // half-warp = pair select
    const int sl   = lane & 15;
    const int gq   = (sl < 12) ? sl : 11;     // l>=1 j-group 0..11
    const bool isG0 = (sl == 12);
    const float act = (sl < 12 || isG0) ? 1.0f : 0.0f;

    int yo, fo0, fstr;
    if (gq < 8) { yo = 5;  fo0 = 64 + 12 * gq;        fstr = 3; }
    else        { yo = 10; fo0 = 160 + 20 * (gq - 8); fstr = 5; }

    float* recW = recS + w * 768;
    const int bbase = 4 * w;

    const float S3  = 1.7320508075688772f;
    const float S5  = 2.2360679774997896f;
    const float S15 = 3.872983346207417f;

    #pragma unroll 1
    for (int chunk = 0; chunk < 4; chunk++) {
        __syncwarp();
        // ---- precompute: lane = pair p (8 a x 4 b) ----
        {
            const int p  = lane;
            const int al = p & 7;
            const int bl = p >> 3;
            const int a  = hf * 32 + chunk * 8 + al;
            const int b  = bbase + bl;
            const float rx = geoS[a * 3 + 0] - geoS[b * 3 + 0];
            const float ry = geoS[a * 3 + 1] - geoS[b * 3 + 1];
            const float rz = geoS[a * 3 + 2] - geoS[b * 3 + 2];
            const float r2 = rx * rx + ry * ry + rz * rz;
            const float r  = sqrtf(fmaxf(r2, 1e-12f));
            const float nzf = (r2 > 1e-10f) ? fs : 0.0f;
            const float inv = 1.0f / r;
            const float xh = rx * inv, yh = ry * inv, zh = rz * inv;

            float* rec = recW + p * 24;
            rec[5]  = S3 * xh * nzf;
            rec[6]  = S3 * yh * nzf;
            rec[7]  = S3 * zh * nzf;
            rec[8]  = 0.0f; rec[9] = 0.0f;
            rec[10] = S15 * xh * yh * nzf;
            rec[11] = S15 * yh * zh * nzf;
            rec[12] = 0.5f * S5 * (3.0f * zh * zh - 1.0f) * nzf;
            rec[13] = S15 * xh * zh * nzf;
            rec[14] = 0.5f * S15 * (xh * xh - yh * yh) * nzf;

            // segment-confined quintic stencil
            float u = r * 37.2f;
            const float sup = (u < 384.0f) ? 1.0f : 0.0f;
            u = fminf(u, 383.99f);
            int sg = (int)(u * 0.0833333333f);
            sg = (sg > 31) ? 31 : sg;
            float xi = u - 12.0f * (float)sg;
            int   nl = (int)xi;
            int   s0 = nl - 2;
            s0 = (s0 < 0) ? 0 : ((s0 > 7) ? 7 : s0);
            const float tt = xi - (float)s0;
            const int gs = 12 * sg + s0;

            const float p0 = tt,        p1 = tt - 1.0f, p2 = tt - 2.0f;
            const float p3 = tt - 3.0f, p4 = tt - 4.0f, p5 = tt - 5.0f;
            const float pr2 = p0 * p1, pr3 = pr2 * p2, pr4 = pr3 * p3, pr5 = pr4 * p4;
            const float sf3 = p4 * p5, sf2 = p3 * sf3, sf1 = p2 * sf2, sf0 = p1 * sf1;
            rec[16] = sup * (-8.3333333333e-3f) * sf0;
            rec[17] = sup * ( 4.1666666667e-2f) * p0 * sf1;
            rec[18] = sup * (-8.3333333333e-2f) * pr2 * sf2;
            rec[19] = sup * ( 8.3333333333e-2f) * pr3 * sf3;
            rec[20] = sup * (-4.1666666667e-2f) * pr4 * p5;
            rec[21] = sup * ( 8.3333333333e-3f) * pr5;
            ((int*)rec)[22] = gs;
        }
        __syncwarp();

        float acc4[4] = {0.f, 0.f, 0.f, 0.f};

        #pragma unroll 1
        for (int bl = 0; bl < 4; bl++) {
            const int b = bbase + bl;
            const float* fbase = rep + (size_t)(z * 64 + b) * 240 + fo0;
            float fr[4][5];
            #pragma unroll
            for (int jj = 0; jj < 4; jj++)
                #pragma unroll
                for (int k = 0; k < 5; k++)
                    fr[jj][k] = __ldg(fbase + fstr * jj + k);

            #pragma unroll
            for (int apL = 0; apL < 4; apL++) {
                const float* rec = recW + (bl * 8 + 2 * apL + hw) * 24;
                const float4 wA = *(const float4*)(rec + 16);
                const float w4  = rec[20];
                const float w5  = rec[21];
                const int   gs  = ((const int*)rec)[22];

                float ct;
                if (isG0) {
                    const float* gp = G0S + gs * 65 + b;
                    ct = wA.x * gp[0];
                    ct = fmaf(wA.y, gp[65],  ct);
                    ct = fmaf(wA.z, gp[130], ct);
                    ct = fmaf(wA.w, gp[195], ct);
                    ct = fmaf(w4,  gp[260], ct);
                    ct = fmaf(w5,  gp[325], ct);
                } else {
                    const float ye0 = rec[yo + 0];
                    const float ye1 = rec[yo + 1];
                    const float ye2 = rec[yo + 2];
                    const float ye3 = rec[yo + 3];
                    const float ye4 = rec[yo + 4];

                    const char* thp = (const char*)THs + gs * 96 + gq * 8;
                    float R0, R1, R2, R3;
                    {
                        uint2 u0 = *(const uint2*)(thp);
                        float2 fa = __half22float2(*(const __half2*)&u0.x);
                        float2 fb = __half22float2(*(const __half2*)&u0.y);
                        R0 = wA.x * fa.x; R1 = wA.x * fa.y;
                        R2 = wA.x * fb.x; R3 = wA.x * fb.y;
                    }
                    {
                        uint2 u1 = *(const uint2*)(thp + 96);
                        float2 fa = __half22float2(*(const __half2*)&u1.x);
                        float2 fb = __half22float2(*(const __half2*)&u1.y);
                        R0 = fmaf(wA.y, fa.x, R0); R1 = fmaf(wA.y, fa.y, R1);
                        R2 = fmaf(wA.y, fb.x, R2); R3 = fmaf(wA.y, fb.y, R3);
                    }
                    {
                        uint2 u2 = *(const uint2*)(thp + 192);
                        float2 fa = __half22float2(*(const __half2*)&u2.x);
                        float2 fb = __half22float2(*(const __half2*)&u2.y);
                        R0 = fmaf(wA.z, fa.x, R0); R1 = fmaf(wA.z, fa.y, R1);
                        R2 = fmaf(wA.z, fb.x, R2); R3 = fmaf(wA.z, fb.y, R3);
                    }
                    {
                        uint2 u3 = *(const uint2*)(thp + 288);
                        float2 fa = __half22float2(*(const __half2*)&u3.x);
                        float2 fb = __half22float2(*(const __half2*)&u3.y);
                        R0 = fmaf(wA.w, fa.x, R0); R1 = fmaf(wA.w, fa.y, R1);
                        R2 = fmaf(wA.w, fb.x, R2); R3 = fmaf(wA.w, fb.y, R3);
                    }
                    {
                        uint2 u4 = *(const uint2*)(thp + 384);
                        float2 fa = __half22float2(*(const __half2*)&u4.x);
                        float2 fb = __half22float2(*(const __half2*)&u4.y);
                        R0 = fmaf(w4, fa.x, R0); R1 = fmaf(w4, fa.y, R1);
                        R2 = fmaf(w4, fb.x, R2); R3 = fmaf(w4, fb.y, R3);
                    }
                    {
                        uint2 u5 = *(const uint2*)(thp + 480);
                        float2 fa = __half22float2(*(const __half2*)&u5.x);
                        float2 fb = __half22float2(*(const __half2*)&u5.y);
                        R0 = fmaf(w5, fa.x, R0); R1 = fmaf(w5, fa.y, R1);
                        R2 = fmaf(w5, fb.x, R2); R3 = fmaf(w5, fb.y, R3);
                    }

                    float F0 = ye0 * fr[0][0]; F0 = fmaf(ye1, fr[0][1], F0);
                    F0 = fmaf(ye2, fr[0][2], F0); F0 = fmaf(ye3, fr[0][3], F0);
                    F0 = fmaf(ye4, fr[0][4], F0);
                    float F1 = ye0 * fr[1][0]; F1 = fmaf(ye1, fr[1][1], F1);
                    F1 = fmaf(ye2, fr[1][2], F1); F1 = fmaf(ye3, fr[1][3], F1);
                    F1 = fmaf(ye4, fr[1][4], F1);
                    float F2 = ye0 * fr[2][0]; F2 = fmaf(ye1, fr[2][1], F2);
                    F2 = fmaf(ye2, fr[2][2], F2); F2 = fmaf(ye3, fr[2][3], F2);
                    F2 = fmaf(ye4, fr[2][4], F2);
                    float F3 = ye0 * fr[3][0]; F3 = fmaf(ye1, fr[3][1], F3);
                    F3 = fmaf(ye2, fr[3][2], F3); F3 = fmaf(ye3, fr[3][3], F3);
                    F3 = fmaf(ye4, fr[3][4], F3);

                    ct = R0 * F0;
                    ct = fmaf(R1, F1, ct);
                    ct = fmaf(R2, F2, ct);
                    ct = fmaf(R3, F3, ct);
                }
                acc4[apL] = fmaf(act, ct, acc4[apL]);
            }
        }

        // ---- reduce within 16-lane halves -> partials ----
        #pragma unroll
        for (int apL = 0; apL < 4; apL++) {
            float v = acc4[apL];
            v += __shfl_xor_sync(0xffffffff, v, 1);
            v += __shfl_xor_sync(0xffffffff, v, 2);
            v += __shfl_xor_sync(0xffffffff, v, 4);
            v += __shfl_xor_sync(0xffffffff, v, 8);
            if (sl == 0) partS[w * 32 + chunk * 8 + 2 * apL + hw] = v;
        }
    }

    __syncthreads();
    if (t < 32) {
        float tot = 0.0f;
        #pragma unroll
        for (int ww = 0; ww < 16; ww++) tot += partS[ww * 32 + t];
        const int aa = hf * 32 + t;
        const float bx = 5.0f * tot;
        const float sp = (fmaxf(bx, 0.0f) + log1pf(expf(-fabsf(bx)))) * 0.2f;
        out[z * 64 + aa] = sp * mask[z * 64 + aa];
    }
}

extern "C" void kernel_launch(void* const* d_in, const int* in_sizes, int n_in,
                              void* d_out, int out_size)
{
    const float* rep  = (const float*)d_in[0];
    const float* geo  = (const float*)d_in[1];
    const float* mask = (const float*)d_in[2];
    const float* W1   = (const float*)d_in[3];
    const float* W2   = (const float*)d_in[4];
    const float* W3   = (const float*)d_in[5];
    float* out = (float*)d_out;

    cudaFuncSetAttribute(build_table_kernel,
                         cudaFuncAttributeMaxDynamicSharedMemorySize, BSMEM_BYTES);
    cudaFuncSetAttribute(output_network_kernel,
                         cudaFuncAttributeMaxDynamicSharedMemorySize, SMEM_BYTES);

    build_table_kernel<<<49, 512, BSMEM_BYTES>>>(W1, W2, W3);
    output_network_kernel<<<GRIDX, THREADS, SMEM_BYTES>>>(rep, geo, mask, out);
}